// round 1
// baseline (speedup 1.0000x reference)
#include <cuda_runtime.h>

#define INDIM 128
#define HIDC  256
#define NBAT  4096
#define N2C   12288
#define FANC  10
#define N1C   122880
#define N0C   1228800

// ---------------- scratch (static device allocations; no cudaMalloc) ----------------
__device__ float g_W0[2 * INDIM * HIDC];            // [256][256]  (Ws0 ; Wn0)
__device__ float g_W1[2 * HIDC * HIDC];             // [512][256]  (Ws1 ; Wn1)
__device__ float g_h0[(size_t)N1C * HIDC];          // 126 MB
__device__ float g_h2[(size_t)N2C * HIDC];
__device__ float g_z1[(size_t)2 * NBAT * HIDC];
__device__ float g_z2[(size_t)2 * NBAT * HIDC];

// ---------------- weight stack: Wout = [Ws ; Wn] along K ----------------
__global__ void concat_kernel(const float* __restrict__ Ws, const float* __restrict__ Wn,
                              float* __restrict__ Wout, int half) {
    int idx = blockIdx.x * 256 + threadIdx.x;
    if (idx < half)            Wout[idx] = Ws[idx];
    else if (idx < 2 * half)   Wout[idx] = Wn[idx - half];
}

// ---------------- fused gather + GEMM ----------------
// MODE 0: A[i] = [node_feat[gids[i]] | mean_f node_feat[gids[neigh[i][f]]]]   (KDIM=256, BM=64)
// MODE 1: A[i] = [h0[i] | mean_f h0[neigh[i][f]]]                             (KDIM=512, BM=32)
// MODE 2: A[i] = h2[i & 4095] * h2[4096 + i]   (elementwise)                  (KDIM=256, BM=32)
// MODE 3: A[i] = src[i]  (plain row-major)                                    (KDIM=256, BM=32)
// out[M,256] = (relu?)(A @ W + bias)
template<int MODE, int BM, int KDIM, bool RELU>
__global__ void __launch_bounds__(256)
gemm_kernel(const float* __restrict__ src,
            const int*   __restrict__ gids,
            const int*   __restrict__ neigh,
            const float* __restrict__ W,
            const float* __restrict__ bias,
            float*       __restrict__ out)
{
    const int LDA = BM + 4;
    extern __shared__ float smem[];
    float* AsT = smem;                 // [KDIM][LDA]   A transposed: AsT[k][row]
    float* Wsh = smem + KDIM * LDA;    // [32][256]     K-chunk of W

    const int tid  = threadIdx.x;
    const int lane = tid & 31;
    const int wid  = tid >> 5;

    // ---------- gather phase: build transposed A tile ----------
    if (MODE == 0) {
        for (int r = wid; r < BM; r += 8) {
            int i = blockIdx.x * BM + r;
            int g = gids[i];
            const float* s = src + (size_t)g * INDIM;
            float self[4], acc[4] = {0.f, 0.f, 0.f, 0.f};
            #pragma unroll
            for (int q = 0; q < 4; q++) self[q] = s[lane + 32 * q];
            #pragma unroll
            for (int f = 0; f < FANC; f++) {
                int nj = neigh[i * FANC + f];
                int gn = gids[nj];
                const float* s2 = src + (size_t)gn * INDIM;
                #pragma unroll
                for (int q = 0; q < 4; q++) acc[q] += s2[lane + 32 * q];
            }
            #pragma unroll
            for (int q = 0; q < 4; q++) {
                AsT[(lane + 32 * q) * LDA + r]         = self[q];
                AsT[(INDIM + lane + 32 * q) * LDA + r] = acc[q] * 0.1f;
            }
        }
    } else if (MODE == 1) {
        for (int r = wid; r < BM; r += 8) {
            int i = blockIdx.x * BM + r;
            const float* s = src + (size_t)i * HIDC;
            float self[8], acc[8];
            #pragma unroll
            for (int q = 0; q < 8; q++) { self[q] = s[lane + 32 * q]; acc[q] = 0.f; }
            #pragma unroll
            for (int f = 0; f < FANC; f++) {
                int nj = neigh[i * FANC + f];
                const float* s2 = src + (size_t)nj * HIDC;
                #pragma unroll
                for (int q = 0; q < 8; q++) acc[q] += s2[lane + 32 * q];
            }
            #pragma unroll
            for (int q = 0; q < 8; q++) {
                AsT[(lane + 32 * q) * LDA + r]        = self[q];
                AsT[(HIDC + lane + 32 * q) * LDA + r] = acc[q] * 0.1f;
            }
        }
    } else if (MODE == 2) {
        for (int r = wid; r < BM; r += 8) {
            int i = blockIdx.x * BM + r;
            const float* a = src + (size_t)(i & (NBAT - 1)) * HIDC;
            const float* b = src + (size_t)(NBAT + i) * HIDC;
            #pragma unroll
            for (int q = 0; q < 8; q++)
                AsT[(lane + 32 * q) * LDA + r] = a[lane + 32 * q] * b[lane + 32 * q];
        }
    } else {
        for (int r = wid; r < BM; r += 8) {
            int i = blockIdx.x * BM + r;
            const float* a = src + (size_t)i * KDIM;
            #pragma unroll
            for (int q = 0; q < KDIM / 32; q++)
                AsT[(lane + 32 * q) * LDA + r] = a[lane + 32 * q];
        }
    }

    // ---------- compute phase ----------
    // thread (ty=wid, tx=lane): rows ty*ROWS..+ROWS-1, cols tx*8..+7
    const int ROWS = BM / 8;
    float acc[BM / 8][8];
    #pragma unroll
    for (int r = 0; r < ROWS; r++)
        #pragma unroll
        for (int q = 0; q < 8; q++) acc[r][q] = 0.f;

    for (int k0 = 0; k0 < KDIM; k0 += 32) {
        __syncthreads();   // gather done / previous chunk consumed
        {
            float4* Wsh4 = (float4*)Wsh;
            const float4* W4 = (const float4*)(W + (size_t)k0 * HIDC);
            #pragma unroll
            for (int j = 0; j < 8; j++) Wsh4[j * 256 + tid] = W4[j * 256 + tid];
        }
        __syncthreads();
        #pragma unroll
        for (int kk = 0; kk < 32; kk++) {
            float a[BM / 8];
            #pragma unroll
            for (int v = 0; v < ROWS / 4; v++) {
                float4 t = *(const float4*)&AsT[(k0 + kk) * LDA + wid * ROWS + v * 4];
                a[v * 4 + 0] = t.x; a[v * 4 + 1] = t.y; a[v * 4 + 2] = t.z; a[v * 4 + 3] = t.w;
            }
            float b[8];
            {
                const float4* bp = (const float4*)&Wsh[kk * HIDC + lane * 8];
                float4 b0 = bp[0], b1 = bp[1];
                b[0]=b0.x; b[1]=b0.y; b[2]=b0.z; b[3]=b0.w;
                b[4]=b1.x; b[5]=b1.y; b[6]=b1.z; b[7]=b1.w;
            }
            #pragma unroll
            for (int r = 0; r < ROWS; r++)
                #pragma unroll
                for (int q = 0; q < 8; q++) acc[r][q] += a[r] * b[q];
        }
    }

    // ---------- epilogue ----------
    const int row0 = blockIdx.x * BM + wid * ROWS;
    const int col0 = lane * 8;
    float bb[8];
    #pragma unroll
    for (int q = 0; q < 8; q++) bb[q] = bias[col0 + q];
    #pragma unroll
    for (int r = 0; r < ROWS; r++) {
        float v[8];
        #pragma unroll
        for (int q = 0; q < 8; q++) {
            v[q] = acc[r][q] + bb[q];
            if (RELU) v[q] = v[q] > 0.f ? v[q] : 0.f;
        }
        float4* op = (float4*)&out[(size_t)(row0 + r) * HIDC + col0];
        op[0] = make_float4(v[0], v[1], v[2], v[3]);
        op[1] = make_float4(v[4], v[5], v[6], v[7]);
    }
}

// ---------------- final score GEMV: out[i] = dot(z[i], Wp3) + bp3 ----------------
__global__ void __launch_bounds__(256)
score_kernel(const float* __restrict__ z, const float* __restrict__ Wp3,
             const float* __restrict__ bp3, float* __restrict__ out) {
    int row  = blockIdx.x * 8 + (threadIdx.x >> 5);
    int lane = threadIdx.x & 31;
    const float* zr = z + (size_t)row * HIDC;
    float s = 0.f;
    #pragma unroll
    for (int q = 0; q < 8; q++) s += zr[lane + 32 * q] * Wp3[lane + 32 * q];
    #pragma unroll
    for (int o = 16; o; o >>= 1) s += __shfl_xor_sync(0xffffffffu, s, o);
    if (lane == 0) out[row] = s + bp3[0];
}

// ---------------- launch ----------------
extern "C" void kernel_launch(void* const* d_in, const int* in_sizes, int n_in,
                              void* d_out, int out_size) {
    const float* node_feat = (const float*)d_in[0];
    const int*   gids0     = (const int*)d_in[1];
    const int*   neigh0    = (const int*)d_in[2];
    const int*   neigh1    = (const int*)d_in[3];
    const float* Ws0       = (const float*)d_in[4];
    const float* Wn0       = (const float*)d_in[5];
    const float* b0        = (const float*)d_in[6];
    const float* Ws1       = (const float*)d_in[7];
    const float* Wn1       = (const float*)d_in[8];
    const float* b1        = (const float*)d_in[9];
    const float* Wp1       = (const float*)d_in[10];
    const float* bp1       = (const float*)d_in[11];
    const float* Wp2       = (const float*)d_in[12];
    const float* bp2       = (const float*)d_in[13];
    const float* Wp3       = (const float*)d_in[14];
    const float* bp3       = (const float*)d_in[15];
    float* out = (float*)d_out;

    float *w0, *w1, *h0, *h2, *z1, *z2;
    cudaGetSymbolAddress((void**)&w0, g_W0);
    cudaGetSymbolAddress((void**)&w1, g_W1);
    cudaGetSymbolAddress((void**)&h0, g_h0);
    cudaGetSymbolAddress((void**)&h2, g_h2);
    cudaGetSymbolAddress((void**)&z1, g_z1);
    cudaGetSymbolAddress((void**)&z2, g_z2);

    const int SM0 = (256 * 68 + 32 * 256) * 4;   // 102400
    const int SM1 = (512 * 36 + 32 * 256) * 4;   // 106496
    const int SM2 = (256 * 36 + 32 * 256) * 4;   //  69632

    cudaFuncSetAttribute(gemm_kernel<0, 64, 256, true>,
                         cudaFuncAttributeMaxDynamicSharedMemorySize, SM0);
    cudaFuncSetAttribute(gemm_kernel<1, 32, 512, false>,
                         cudaFuncAttributeMaxDynamicSharedMemorySize, SM1);
    cudaFuncSetAttribute(gemm_kernel<2, 32, 256, true>,
                         cudaFuncAttributeMaxDynamicSharedMemorySize, SM2);
    cudaFuncSetAttribute(gemm_kernel<3, 32, 256, true>,
                         cudaFuncAttributeMaxDynamicSharedMemorySize, SM2);

    // stack weights: [Ws ; Wn] along K
    concat_kernel<<<256, 256>>>(Ws0, Wn0, w0, INDIM * HIDC);      // 2*32768 elems
    concat_kernel<<<512, 256>>>(Ws1, Wn1, w1, HIDC * HIDC);       // 2*65536 elems

    // layer 0: h0 = relu([x_self | mean_neigh] @ W0 + b0)
    gemm_kernel<0, 64, 256, true><<<N1C / 64, 256, SM0>>>(node_feat, gids0, neigh0, w0, b0, h0);
    // layer 1: h2 = [h0_self | mean_neigh] @ W1 + b1    (no relu)
    gemm_kernel<1, 32, 512, false><<<N2C / 32, 256, SM1>>>(h0, nullptr, neigh1, w1, b1, h2);
    // MLP1: z1 = relu((src*posneg) @ Wp1 + bp1)
    gemm_kernel<2, 32, 256, true><<<(2 * NBAT) / 32, 256, SM2>>>(h2, nullptr, nullptr, Wp1, bp1, z1);
    // MLP2: z2 = relu(z1 @ Wp2 + bp2)
    gemm_kernel<3, 32, 256, true><<<(2 * NBAT) / 32, 256, SM2>>>(z1, nullptr, nullptr, Wp2, bp2, z2);
    // scores
    score_kernel<<<(2 * NBAT) / 8, 256>>>(z2, Wp3, bp3, out);
}

// round 3
// speedup vs baseline: 1.3485x; 1.3485x over previous
#include <cuda_runtime.h>
#include <cuda_bf16.h>
#include <cstdint>

#define INDIM 128
#define HIDC  256
#define NBAT  4096
#define N2C   12288
#define FANC  10
#define N1C   122880

// ---------------- scratch (static device allocations; no cudaMalloc) ----------------
__device__ float g_h0[(size_t)N1C * HIDC];
__device__ float g_h2[(size_t)N2C * HIDC];
__device__ float g_z1[(size_t)2 * NBAT * HIDC];
__device__ float g_z2[(size_t)2 * NBAT * HIDC];

// ---------------- bf16 split helpers ----------------
__device__ __forceinline__ void split_pack(float a, float b, uint32_t& hi, uint32_t& lo) {
    __nv_bfloat16 ha = __float2bfloat16_rn(a);
    __nv_bfloat16 hb = __float2bfloat16_rn(b);
    float la = a - __bfloat162float(ha);
    float lb = b - __bfloat162float(hb);
    __nv_bfloat16 sa = __float2bfloat16_rn(la);
    __nv_bfloat16 sb = __float2bfloat16_rn(lb);
    hi = ((uint32_t)__bfloat16_as_ushort(hb) << 16) | (uint32_t)__bfloat16_as_ushort(ha);
    lo = ((uint32_t)__bfloat16_as_ushort(sb) << 16) | (uint32_t)__bfloat16_as_ushort(sa);
}

__device__ __forceinline__ void store_split4(uint32_t* Ahi, uint32_t* Alo, int idx, float4 v) {
    uint32_t h0, l0, h1, l1;
    split_pack(v.x, v.y, h0, l0);
    split_pack(v.z, v.w, h1, l1);
    *(uint2*)&Ahi[idx] = make_uint2(h0, h1);
    *(uint2*)&Alo[idx] = make_uint2(l0, l1);
}

#define MMA_BF16(c, a, b0v, b1v) \
    asm volatile("mma.sync.aligned.m16n8k16.row.col.f32.bf16.bf16.f32 " \
        "{%0,%1,%2,%3}, {%4,%5,%6,%7}, {%8,%9}, {%0,%1,%2,%3};" \
        : "+f"((c)[0]), "+f"((c)[1]), "+f"((c)[2]), "+f"((c)[3]) \
        : "r"((a)[0]), "r"((a)[1]), "r"((a)[2]), "r"((a)[3]), "r"(b0v), "r"(b1v))

// ---------------- fused gather + bf16x3-split tensor-core GEMM ----------------
// out[128/CTA, 256] = (relu?)( sum_pass A_pass @ W_pass + bias )
// MODE 0: pass0 A=node_feat[gids[i]] (KP=128), pass1 A=mean_f node_feat[gids[neigh[i][f]]]
// MODE 1: pass0 A=h0[i] (KP=256),    pass1 A=mean_f h0[neigh[i][f]]
// MODE 2: A = h2[i&4095] * h2[4096+i]  (KP=256, 1 pass)
// MODE 3: A = src[i]                   (KP=256, 1 pass)
template<int MODE, int KP, int NPASS, bool RELU>
__global__ void __launch_bounds__(512, 1)
mma_gemm(const float* __restrict__ src,
         const int*   __restrict__ gids,
         const int*   __restrict__ neigh,
         const float* __restrict__ W0,   // [KP][256] row-major
         const float* __restrict__ W1,   // [KP][256] row-major (pass 1)
         const float* __restrict__ bias,
         float*       __restrict__ out)
{
    constexpr int LDA_U = KP / 2 + 4;            // packed-u32 row stride of A
    constexpr int A_U   = 128 * LDA_U;
    constexpr int LDB_U = 264;                   // packed-u32 row stride of B chunk
    constexpr int B_U   = 16 * LDB_U;

    extern __shared__ uint32_t smem[];
    uint32_t* Ahi = smem;
    uint32_t* Alo = Ahi + A_U;
    uint32_t* Bhi = Alo + A_U;
    uint32_t* Blo = Bhi + B_U;
    float*    bsm = (float*)(Blo + B_U);

    const int tid  = threadIdx.x;
    const int lane = tid & 31;
    const int wid  = tid >> 5;
    const int wr   = wid >> 2;      // warp row 0..3  (32 rows each)
    const int wc   = wid & 3;       // warp col 0..3  (64 cols each)
    const float4* src4 = (const float4*)src;

    if (tid < 256) bsm[tid] = bias[tid];

    float acc[2][8][4];
    #pragma unroll
    for (int mt = 0; mt < 2; mt++)
        #pragma unroll
        for (int nt = 0; nt < 8; nt++)
            #pragma unroll
            for (int q = 0; q < 4; q++) acc[mt][nt][q] = 0.f;

    #pragma unroll 1
    for (int pass = 0; pass < NPASS; pass++) {
        const float* W = (pass == 0) ? W0 : W1;

        // ---------- gather A tile (fp32 -> split bf16 hi/lo, packed pairs) ----------
        if (MODE == 0) {
            if (pass == 0) {
                for (int r = wid; r < 128; r += 16) {
                    int i = blockIdx.x * 128 + r;
                    int g = __ldg(&gids[i]);
                    float4 v = __ldg(&src4[(size_t)g * 32 + lane]);
                    store_split4(Ahi, Alo, r * LDA_U + 2 * lane, v);
                }
            } else {
                #pragma unroll 2
                for (int r = wid; r < 128; r += 16) {
                    int i = blockIdx.x * 128 + r;
                    const int* nb = neigh + (size_t)i * FANC;
                    float4 a = make_float4(0.f, 0.f, 0.f, 0.f);
                    #pragma unroll
                    for (int f = 0; f < FANC; f++) {
                        int nj = __ldg(&nb[f]);
                        int gn = __ldg(&gids[nj]);
                        float4 t = __ldg(&src4[(size_t)gn * 32 + lane]);
                        a.x += t.x; a.y += t.y; a.z += t.z; a.w += t.w;
                    }
                    store_split4(Ahi, Alo, r * LDA_U + 2 * lane,
                                 make_float4(a.x * 0.1f, a.y * 0.1f, a.z * 0.1f, a.w * 0.1f));
                }
            }
        } else if (MODE == 1) {
            if (pass == 0) {
                for (int r = wid; r < 128; r += 16) {
                    int i = blockIdx.x * 128 + r;
                    #pragma unroll
                    for (int h = 0; h < 2; h++) {
                        float4 v = __ldg(&src4[(size_t)i * 64 + lane + 32 * h]);
                        store_split4(Ahi, Alo, r * LDA_U + 2 * (lane + 32 * h), v);
                    }
                }
            } else {
                #pragma unroll 2
                for (int r = wid; r < 128; r += 16) {
                    int i = blockIdx.x * 128 + r;
                    const int* nb = neigh + (size_t)i * FANC;
                    float4 a0 = make_float4(0.f, 0.f, 0.f, 0.f);
                    float4 a1 = make_float4(0.f, 0.f, 0.f, 0.f);
                    #pragma unroll
                    for (int f = 0; f < FANC; f++) {
                        int nj = __ldg(&nb[f]);
                        const float4* p = src4 + (size_t)nj * 64;
                        float4 t0 = __ldg(p + lane);
                        float4 t1 = __ldg(p + lane + 32);
                        a0.x += t0.x; a0.y += t0.y; a0.z += t0.z; a0.w += t0.w;
                        a1.x += t1.x; a1.y += t1.y; a1.z += t1.z; a1.w += t1.w;
                    }
                    store_split4(Ahi, Alo, r * LDA_U + 2 * lane,
                                 make_float4(a0.x * 0.1f, a0.y * 0.1f, a0.z * 0.1f, a0.w * 0.1f));
                    store_split4(Ahi, Alo, r * LDA_U + 2 * (lane + 32),
                                 make_float4(a1.x * 0.1f, a1.y * 0.1f, a1.z * 0.1f, a1.w * 0.1f));
                }
            }
        } else if (MODE == 2) {
            for (int r = wid; r < 128; r += 16) {
                int i = blockIdx.x * 128 + r;
                const float4* pa = src4 + (size_t)(i & (NBAT - 1)) * 64;
                const float4* pb = src4 + (size_t)(NBAT + i) * 64;
                #pragma unroll
                for (int h = 0; h < 2; h++) {
                    float4 x = __ldg(pa + lane + 32 * h);
                    float4 y = __ldg(pb + lane + 32 * h);
                    store_split4(Ahi, Alo, r * LDA_U + 2 * (lane + 32 * h),
                                 make_float4(x.x * y.x, x.y * y.y, x.z * y.z, x.w * y.w));
                }
            }
        } else {
            for (int r = wid; r < 128; r += 16) {
                int i = blockIdx.x * 128 + r;
                #pragma unroll
                for (int h = 0; h < 2; h++) {
                    float4 v = __ldg(&src4[(size_t)i * 64 + lane + 32 * h]);
                    store_split4(Ahi, Alo, r * LDA_U + 2 * (lane + 32 * h), v);
                }
            }
        }

        // ---------- K chunks of 32: stage B (split), then MMA ----------
        #pragma unroll 1
        for (int c = 0; c < KP / 32; c++) {
            for (int e = tid; e < 16 * 256; e += 512) {
                int kp  = e >> 8;
                int col = e & 255;
                int krow = c * 32 + 2 * kp;
                float w0 = __ldg(&W[(size_t)krow * 256 + col]);
                float w1 = __ldg(&W[(size_t)(krow + 1) * 256 + col]);
                uint32_t h, l;
                split_pack(w0, w1, h, l);
                Bhi[kp * LDB_U + col] = h;
                Blo[kp * LDB_U + col] = l;
            }
            __syncthreads();

            #pragma unroll
            for (int ks = 0; ks < 2; ks++) {
                const int kpo = c * 16 + ks * 8;
                uint32_t ah[2][4], al[2][4];
                const int abase = (wr * 32 + (lane >> 2)) * LDA_U + (lane & 3) + kpo;
                #pragma unroll
                for (int mt = 0; mt < 2; mt++) {
                    int a0i = abase + mt * 16 * LDA_U;
                    ah[mt][0] = Ahi[a0i];
                    ah[mt][1] = Ahi[a0i + 8 * LDA_U];
                    ah[mt][2] = Ahi[a0i + 4];
                    ah[mt][3] = Ahi[a0i + 8 * LDA_U + 4];
                    al[mt][0] = Alo[a0i];
                    al[mt][1] = Alo[a0i + 8 * LDA_U];
                    al[mt][2] = Alo[a0i + 4];
                    al[mt][3] = Alo[a0i + 8 * LDA_U + 4];
                }
                const int bbase = (ks * 8 + (lane & 3)) * LDB_U + wc * 64 + (lane >> 2);
                #pragma unroll
                for (int nt = 0; nt < 8; nt++) {
                    int bi = bbase + nt * 8;
                    uint32_t bh0 = Bhi[bi], bh1 = Bhi[bi + 4 * LDB_U];
                    uint32_t bl0 = Blo[bi], bl1 = Blo[bi + 4 * LDB_U];
                    #pragma unroll
                    for (int mt = 0; mt < 2; mt++) {
                        MMA_BF16(acc[mt][nt], ah[mt], bh0, bh1);
                        MMA_BF16(acc[mt][nt], ah[mt], bl0, bl1);
                        MMA_BF16(acc[mt][nt], al[mt], bh0, bh1);
                    }
                }
            }
            __syncthreads();
        }
    }

    // ---------- epilogue: bias (+relu), float2 stores ----------
    const int row0 = blockIdx.x * 128 + wr * 32 + (lane >> 2);
    #pragma unroll
    for (int mt = 0; mt < 2; mt++) {
        #pragma unroll
        for (int nt = 0; nt < 8; nt++) {
            int col = wc * 64 + nt * 8 + 2 * (lane & 3);
            float b0 = bsm[col], b1 = bsm[col + 1];
            float v0 = acc[mt][nt][0] + b0;
            float v1 = acc[mt][nt][1] + b1;
            float v2 = acc[mt][nt][2] + b0;
            float v3 = acc[mt][nt][3] + b1;
            if (RELU) {
                v0 = fmaxf(v0, 0.f); v1 = fmaxf(v1, 0.f);
                v2 = fmaxf(v2, 0.f); v3 = fmaxf(v3, 0.f);
            }
            int r = row0 + mt * 16;
            *(float2*)&out[(size_t)r * HIDC + col]       = make_float2(v0, v1);
            *(float2*)&out[(size_t)(r + 8) * HIDC + col] = make_float2(v2, v3);
        }
    }
}

// ---------------- final score GEMV ----------------
__global__ void __launch_bounds__(256)
score_kernel(const float* __restrict__ z, const float* __restrict__ Wp3,
             const float* __restrict__ bp3, float* __restrict__ out) {
    int row  = blockIdx.x * 8 + (threadIdx.x >> 5);
    int lane = threadIdx.x & 31;
    const float* zr = z + (size_t)row * HIDC;
    float s = 0.f;
    #pragma unroll
    for (int q = 0; q < 8; q++) s += zr[lane + 32 * q] * Wp3[lane + 32 * q];
    #pragma unroll
    for (int o = 16; o; o >>= 1) s += __shfl_xor_sync(0xffffffffu, s, o);
    if (lane == 0) out[row] = s + bp3[0];
}

// ---------------- launch ----------------
extern "C" void kernel_launch(void* const* d_in, const int* in_sizes, int n_in,
                              void* d_out, int out_size) {
    const float* node_feat = (const float*)d_in[0];
    const int*   gids0     = (const int*)d_in[1];
    const int*   neigh0    = (const int*)d_in[2];
    const int*   neigh1    = (const int*)d_in[3];
    const float* Ws0       = (const float*)d_in[4];
    const float* Wn0       = (const float*)d_in[5];
    const float* b0        = (const float*)d_in[6];
    const float* Ws1       = (const float*)d_in[7];
    const float* Wn1       = (const float*)d_in[8];
    const float* b1        = (const float*)d_in[9];
    const float* Wp1       = (const float*)d_in[10];
    const float* bp1       = (const float*)d_in[11];
    const float* Wp2       = (const float*)d_in[12];
    const float* bp2       = (const float*)d_in[13];
    const float* Wp3       = (const float*)d_in[14];
    const float* bp3       = (const float*)d_in[15];
    float* out = (float*)d_out;

    float *h0, *h2, *z1, *z2;
    cudaGetSymbolAddress((void**)&h0, g_h0);
    cudaGetSymbolAddress((void**)&h2, g_h2);
    cudaGetSymbolAddress((void**)&z1, g_z1);
    cudaGetSymbolAddress((void**)&z2, g_z2);

    // smem bytes: 2*A + 2*B + bias
    const int SM128 = (2 * 128 * (128 / 2 + 4) + 2 * 16 * 264) * 4 + 1024;  // 104,448
    const int SM256 = (2 * 128 * (256 / 2 + 4) + 2 * 16 * 264) * 4 + 1024;  // 169,984

    cudaFuncSetAttribute(mma_gemm<0, 128, 2, true >, cudaFuncAttributeMaxDynamicSharedMemorySize, SM128);
    cudaFuncSetAttribute(mma_gemm<1, 256, 2, false>, cudaFuncAttributeMaxDynamicSharedMemorySize, SM256);
    cudaFuncSetAttribute(mma_gemm<2, 256, 1, true >, cudaFuncAttributeMaxDynamicSharedMemorySize, SM256);
    cudaFuncSetAttribute(mma_gemm<3, 256, 1, true >, cudaFuncAttributeMaxDynamicSharedMemorySize, SM256);

    // layer 0: h0 = relu(self@Ws0 + mean@Wn0 + b0)
    mma_gemm<0, 128, 2, true ><<<N1C / 128, 512, SM128>>>(node_feat, gids0, neigh0, Ws0, Wn0, b0, h0);
    // layer 1: h2 = self@Ws1 + mean@Wn1 + b1
    mma_gemm<1, 256, 2, false><<<N2C / 128, 512, SM256>>>(h0, nullptr, neigh1, Ws1, Wn1, b1, h2);
    // MLP1: z1 = relu((src*posneg)@Wp1 + bp1)
    mma_gemm<2, 256, 1, true ><<<(2 * NBAT) / 128, 512, SM256>>>(h2, nullptr, nullptr, Wp1, nullptr, bp1, z1);
    // MLP2: z2 = relu(z1@Wp2 + bp2)
    mma_gemm<3, 256, 1, true ><<<(2 * NBAT) / 128, 512, SM256>>>(z1, nullptr, nullptr, Wp2, nullptr, bp2, z2);
    // scores
    score_kernel<<<(2 * NBAT) / 8, 256>>>(z2, Wp3, bp3, out);
}

// round 4
// speedup vs baseline: 1.4646x; 1.0861x over previous
#include <cuda_runtime.h>
#include <cuda_bf16.h>
#include <cstdint>

#define INDIM 128
#define HIDC  256
#define NBAT  4096
#define N2C   12288
#define FANC  10
#define N1C   122880

// ---------------- scratch (static device allocations; no cudaMalloc) ----------------
__device__ float g_h0[(size_t)N1C * HIDC];
__device__ float g_h2[(size_t)N2C * HIDC];

// ---------------- bf16 split helpers ----------------
__device__ __forceinline__ void split_pack(float a, float b, uint32_t& hi, uint32_t& lo) {
    __nv_bfloat16 ha = __float2bfloat16_rn(a);
    __nv_bfloat16 hb = __float2bfloat16_rn(b);
    float la = a - __bfloat162float(ha);
    float lb = b - __bfloat162float(hb);
    __nv_bfloat16 sa = __float2bfloat16_rn(la);
    __nv_bfloat16 sb = __float2bfloat16_rn(lb);
    hi = ((uint32_t)__bfloat16_as_ushort(hb) << 16) | (uint32_t)__bfloat16_as_ushort(ha);
    lo = ((uint32_t)__bfloat16_as_ushort(sb) << 16) | (uint32_t)__bfloat16_as_ushort(sa);
}

__device__ __forceinline__ void store_split4(uint32_t* Ahi, uint32_t* Alo, int idx, float4 v) {
    uint32_t h0, l0, h1, l1;
    split_pack(v.x, v.y, h0, l0);
    split_pack(v.z, v.w, h1, l1);
    *(uint2*)&Ahi[idx] = make_uint2(h0, h1);
    *(uint2*)&Alo[idx] = make_uint2(l0, l1);
}

#define MMA_BF16(c, a, b0v, b1v) \
    asm volatile("mma.sync.aligned.m16n8k16.row.col.f32.bf16.bf16.f32 " \
        "{%0,%1,%2,%3}, {%4,%5,%6,%7}, {%8,%9}, {%0,%1,%2,%3};" \
        : "+f"((c)[0]), "+f"((c)[1]), "+f"((c)[2]), "+f"((c)[3]) \
        : "r"((a)[0]), "r"((a)[1]), "r"((a)[2]), "r"((a)[3]), "r"(b0v), "r"(b1v))

// ---------------- fused gather + bf16x3-split tensor-core GEMM (layers 0/1) ----------------
// out[128/CTA, 256] = (relu?)( A_self @ W0 + A_mean @ W1 + bias )
// MODE 0: self=node_feat[gids[i]] (KP=128), mean over node_feat[gids[neigh[i][f]]]
// MODE 1: self=h0[i] (KP=256),              mean over h0[neigh[i][f]]
template<int MODE, int KP, bool RELU>
__global__ void __launch_bounds__(512, 1)
mma_gemm(const float* __restrict__ src,
         const int*   __restrict__ gids,
         const int*   __restrict__ neigh,
         const float* __restrict__ W0,   // [KP][256] row-major
         const float* __restrict__ W1,   // [KP][256] row-major (neighbor pass)
         const float* __restrict__ bias,
         float*       __restrict__ out)
{
    constexpr int LDA_U = KP / 2 + 4;            // packed-u32 row stride of A
    constexpr int A_U   = 128 * LDA_U;
    constexpr int LDB_U = 264;                   // packed-u32 row stride of B chunk
    constexpr int B_U   = 16 * LDB_U;

    extern __shared__ uint32_t smem[];
    uint32_t* Ahi = smem;
    uint32_t* Alo = Ahi + A_U;
    uint32_t* Bhi = Alo + A_U;
    uint32_t* Blo = Bhi + B_U;
    float*    bsm = (float*)(Blo + B_U);
    int*      gidx = (int*)(bsm + 256);          // 1280 resolved neighbor row ids

    const int tid  = threadIdx.x;
    const int lane = tid & 31;
    const int wid  = tid >> 5;
    const int wr   = wid >> 2;      // warp row 0..3  (32 rows each)
    const int wc   = wid & 3;       // warp col 0..3  (64 cols each)
    const float4* src4 = (const float4*)src;

    if (tid < 256) bsm[tid] = bias[tid];

    // ---------- pre-resolve neighbor indices (kills the dependent-load chain) ----------
    for (int e = tid; e < 128 * FANC; e += 512) {
        int nj = __ldg(&neigh[(size_t)blockIdx.x * 128 * FANC + e]);
        gidx[e] = (MODE == 0) ? __ldg(&gids[nj]) : nj;
    }

    float acc[2][8][4];
    #pragma unroll
    for (int mt = 0; mt < 2; mt++)
        #pragma unroll
        for (int nt = 0; nt < 8; nt++)
            #pragma unroll
            for (int q = 0; q < 4; q++) acc[mt][nt][q] = 0.f;

    #pragma unroll 1
    for (int pass = 0; pass < 2; pass++) {
        const float* W = (pass == 0) ? W0 : W1;

        // ---------- gather A tile (fp32 -> split bf16 hi/lo, packed pairs) ----------
        if (MODE == 0) {
            if (pass == 0) {
                for (int r = wid; r < 128; r += 16) {
                    int i = blockIdx.x * 128 + r;
                    int g = __ldg(&gids[i]);
                    float4 v = __ldg(&src4[(size_t)g * 32 + lane]);
                    store_split4(Ahi, Alo, r * LDA_U + 2 * lane, v);
                }
            } else {
                #pragma unroll 1
                for (int g = 0; g < 2; g++) {
                    float4 a[4];
                    #pragma unroll
                    for (int j = 0; j < 4; j++) a[j] = make_float4(0.f, 0.f, 0.f, 0.f);
                    #pragma unroll
                    for (int f = 0; f < FANC; f++) {
                        #pragma unroll
                        for (int j = 0; j < 4; j++) {
                            int rr = wid + 16 * (g * 4 + j);
                            int gn = gidx[rr * FANC + f];
                            float4 t = __ldg(&src4[(size_t)gn * 32 + lane]);
                            a[j].x += t.x; a[j].y += t.y; a[j].z += t.z; a[j].w += t.w;
                        }
                    }
                    #pragma unroll
                    for (int j = 0; j < 4; j++) {
                        int rr = wid + 16 * (g * 4 + j);
                        store_split4(Ahi, Alo, rr * LDA_U + 2 * lane,
                                     make_float4(a[j].x * 0.1f, a[j].y * 0.1f,
                                                 a[j].z * 0.1f, a[j].w * 0.1f));
                    }
                }
            }
        } else {
            if (pass == 0) {
                for (int r = wid; r < 128; r += 16) {
                    int i = blockIdx.x * 128 + r;
                    #pragma unroll
                    for (int h = 0; h < 2; h++) {
                        float4 v = __ldg(&src4[(size_t)i * 64 + lane + 32 * h]);
                        store_split4(Ahi, Alo, r * LDA_U + 2 * (lane + 32 * h), v);
                    }
                }
            } else {
                #pragma unroll 1
                for (int g = 0; g < 4; g++) {
                    float4 a0[2], a1[2];
                    #pragma unroll
                    for (int j = 0; j < 2; j++) {
                        a0[j] = make_float4(0.f, 0.f, 0.f, 0.f);
                        a1[j] = make_float4(0.f, 0.f, 0.f, 0.f);
                    }
                    #pragma unroll
                    for (int f = 0; f < FANC; f++) {
                        #pragma unroll
                        for (int j = 0; j < 2; j++) {
                            int rr = wid + 16 * (g * 2 + j);
                            int nj = gidx[rr * FANC + f];
                            const float4* p = src4 + (size_t)nj * 64;
                            float4 t0 = __ldg(p + lane);
                            float4 t1 = __ldg(p + lane + 32);
                            a0[j].x += t0.x; a0[j].y += t0.y; a0[j].z += t0.z; a0[j].w += t0.w;
                            a1[j].x += t1.x; a1[j].y += t1.y; a1[j].z += t1.z; a1[j].w += t1.w;
                        }
                    }
                    #pragma unroll
                    for (int j = 0; j < 2; j++) {
                        int rr = wid + 16 * (g * 2 + j);
                        store_split4(Ahi, Alo, rr * LDA_U + 2 * lane,
                                     make_float4(a0[j].x * 0.1f, a0[j].y * 0.1f,
                                                 a0[j].z * 0.1f, a0[j].w * 0.1f));
                        store_split4(Ahi, Alo, rr * LDA_U + 2 * (lane + 32),
                                     make_float4(a1[j].x * 0.1f, a1[j].y * 0.1f,
                                                 a1[j].z * 0.1f, a1[j].w * 0.1f));
                    }
                }
            }
        }

        // ---------- K chunks of 32: stage B (split), then MMA ----------
        #pragma unroll 1
        for (int c = 0; c < KP / 32; c++) {
            for (int e = tid; e < 16 * 256; e += 512) {
                int kp  = e >> 8;
                int col = e & 255;
                int krow = c * 32 + 2 * kp;
                float w0 = __ldg(&W[(size_t)krow * 256 + col]);
                float w1 = __ldg(&W[(size_t)(krow + 1) * 256 + col]);
                uint32_t h, l;
                split_pack(w0, w1, h, l);
                Bhi[kp * LDB_U + col] = h;
                Blo[kp * LDB_U + col] = l;
            }
            __syncthreads();

            #pragma unroll
            for (int ks = 0; ks < 2; ks++) {
                const int kpo = c * 16 + ks * 8;
                uint32_t ah[2][4], al[2][4];
                const int abase = (wr * 32 + (lane >> 2)) * LDA_U + (lane & 3) + kpo;
                #pragma unroll
                for (int mt = 0; mt < 2; mt++) {
                    int a0i = abase + mt * 16 * LDA_U;
                    ah[mt][0] = Ahi[a0i];
                    ah[mt][1] = Ahi[a0i + 8 * LDA_U];
                    ah[mt][2] = Ahi[a0i + 4];
                    ah[mt][3] = Ahi[a0i + 8 * LDA_U + 4];
                    al[mt][0] = Alo[a0i];
                    al[mt][1] = Alo[a0i + 8 * LDA_U];
                    al[mt][2] = Alo[a0i + 4];
                    al[mt][3] = Alo[a0i + 8 * LDA_U + 4];
                }
                const int bbase = (ks * 8 + (lane & 3)) * LDB_U + wc * 64 + (lane >> 2);
                #pragma unroll
                for (int nt = 0; nt < 8; nt++) {
                    int bi = bbase + nt * 8;
                    uint32_t bh0 = Bhi[bi], bh1 = Bhi[bi + 4 * LDB_U];
                    uint32_t bl0 = Blo[bi], bl1 = Blo[bi + 4 * LDB_U];
                    #pragma unroll
                    for (int mt = 0; mt < 2; mt++) {
                        MMA_BF16(acc[mt][nt], ah[mt], bh0, bh1);
                        MMA_BF16(acc[mt][nt], ah[mt], bl0, bl1);
                        MMA_BF16(acc[mt][nt], al[mt], bh0, bh1);
                    }
                }
            }
            __syncthreads();
        }
    }

    // ---------- epilogue: bias (+relu), float2 stores ----------
    const int row0 = blockIdx.x * 128 + wr * 32 + (lane >> 2);
    #pragma unroll
    for (int mt = 0; mt < 2; mt++) {
        #pragma unroll
        for (int nt = 0; nt < 8; nt++) {
            int col = wc * 64 + nt * 8 + 2 * (lane & 3);
            float b0 = bsm[col], b1 = bsm[col + 1];
            float v0 = acc[mt][nt][0] + b0;
            float v1 = acc[mt][nt][1] + b1;
            float v2 = acc[mt][nt][2] + b0;
            float v3 = acc[mt][nt][3] + b1;
            if (RELU) {
                v0 = fmaxf(v0, 0.f); v1 = fmaxf(v1, 0.f);
                v2 = fmaxf(v2, 0.f); v3 = fmaxf(v3, 0.f);
            }
            int r = row0 + mt * 16;
            *(float2*)&out[(size_t)r * HIDC + col]       = make_float2(v0, v1);
            *(float2*)&out[(size_t)(r + 8) * HIDC + col] = make_float2(v2, v3);
        }
    }
}

// ---------------- fused MLP1 + MLP2 + score (row-local chain) ----------------
// block: 64 rows of the 8192 edge rows; 256 threads, 2 CTAs/SM
__global__ void __launch_bounds__(256, 2)
mlp_fused(const float* __restrict__ h2,
          const float* __restrict__ Wp1, const float* __restrict__ bp1,
          const float* __restrict__ Wp2, const float* __restrict__ bp2,
          const float* __restrict__ Wp3, const float* __restrict__ bp3,
          float* __restrict__ out)
{
    constexpr int LDA_U = 132;          // K=256 packed pairs + pad
    constexpr int A_U   = 64 * LDA_U;
    constexpr int LDB_U = 264;
    constexpr int B_U   = 16 * LDB_U;

    extern __shared__ uint32_t smem[];
    uint32_t* Ahi = smem;
    uint32_t* Alo = Ahi + A_U;
    uint32_t* Bhi = Alo + A_U;
    uint32_t* Blo = Bhi + B_U;
    float* bsm1 = (float*)(Blo + B_U);
    float* bsm2 = bsm1 + 256;
    float* w3   = bsm2 + 256;
    float* sred = w3 + 256;

    const int tid  = threadIdx.x;
    const int lane = tid & 31;
    const int wid  = tid >> 5;
    const int wr   = wid >> 2;   // 0..1  (32 rows each)
    const int wc   = wid & 3;    // 0..3  (64 cols each)
    const float4* src4 = (const float4*)h2;

    bsm1[tid] = bp1[tid];
    bsm2[tid] = bp2[tid];
    w3[tid]   = Wp3[tid];
    if (tid < 64) sred[tid] = bp3[0];

    // ---------- build A = src * posneg ----------
    for (int r = wid; r < 64; r += 8) {
        int i = blockIdx.x * 64 + r;
        const float4* pa = src4 + (size_t)(i & (NBAT - 1)) * 64;
        const float4* pb = src4 + (size_t)(NBAT + i) * 64;
        #pragma unroll
        for (int h = 0; h < 2; h++) {
            float4 x = __ldg(pa + lane + 32 * h);
            float4 y = __ldg(pb + lane + 32 * h);
            store_split4(Ahi, Alo, r * LDA_U + 2 * (lane + 32 * h),
                         make_float4(x.x * y.x, x.y * y.y, x.z * y.z, x.w * y.w));
        }
    }

    float acc[2][8][4];

    // ---------- two GEMM layers ----------
    #pragma unroll 1
    for (int layer = 0; layer < 2; layer++) {
        const float* W = (layer == 0) ? Wp1 : Wp2;

        #pragma unroll
        for (int mt = 0; mt < 2; mt++)
            #pragma unroll
            for (int nt = 0; nt < 8; nt++)
                #pragma unroll
                for (int q = 0; q < 4; q++) acc[mt][nt][q] = 0.f;

        #pragma unroll 1
        for (int c = 0; c < 8; c++) {
            for (int e = tid; e < 16 * 256; e += 256) {
                int kp  = e >> 8;
                int col = e & 255;
                int krow = c * 32 + 2 * kp;
                float w0 = __ldg(&W[(size_t)krow * 256 + col]);
                float w1 = __ldg(&W[(size_t)(krow + 1) * 256 + col]);
                uint32_t h, l;
                split_pack(w0, w1, h, l);
                Bhi[kp * LDB_U + col] = h;
                Blo[kp * LDB_U + col] = l;
            }
            __syncthreads();

            #pragma unroll
            for (int ks = 0; ks < 2; ks++) {
                const int kpo = c * 16 + ks * 8;
                uint32_t ah[2][4], al[2][4];
                const int abase = (wr * 32 + (lane >> 2)) * LDA_U + (lane & 3) + kpo;
                #pragma unroll
                for (int mt = 0; mt < 2; mt++) {
                    int a0i = abase + mt * 16 * LDA_U;
                    ah[mt][0] = Ahi[a0i];
                    ah[mt][1] = Ahi[a0i + 8 * LDA_U];
                    ah[mt][2] = Ahi[a0i + 4];
                    ah[mt][3] = Ahi[a0i + 8 * LDA_U + 4];
                    al[mt][0] = Alo[a0i];
                    al[mt][1] = Alo[a0i + 8 * LDA_U];
                    al[mt][2] = Alo[a0i + 4];
                    al[mt][3] = Alo[a0i + 8 * LDA_U + 4];
                }
                const int bbase = (ks * 8 + (lane & 3)) * LDB_U + wc * 64 + (lane >> 2);
                #pragma unroll
                for (int nt = 0; nt < 8; nt++) {
                    int bi = bbase + nt * 8;
                    uint32_t bh0 = Bhi[bi], bh1 = Bhi[bi + 4 * LDB_U];
                    uint32_t bl0 = Blo[bi], bl1 = Blo[bi + 4 * LDB_U];
                    #pragma unroll
                    for (int mt = 0; mt < 2; mt++) {
                        MMA_BF16(acc[mt][nt], ah[mt], bh0, bh1);
                        MMA_BF16(acc[mt][nt], ah[mt], bl0, bl1);
                        MMA_BF16(acc[mt][nt], al[mt], bh0, bh1);
                    }
                }
            }
            __syncthreads();
        }

        if (layer == 0) {
            // write z1 = relu(acc + bp1) back into the split-A region
            #pragma unroll
            for (int mt = 0; mt < 2; mt++) {
                int r = wr * 32 + (lane >> 2) + mt * 16;
                #pragma unroll
                for (int nt = 0; nt < 8; nt++) {
                    int col = wc * 64 + nt * 8 + 2 * (lane & 3);
                    float b0 = bsm1[col], b1 = bsm1[col + 1];
                    float v0 = fmaxf(acc[mt][nt][0] + b0, 0.f);
                    float v1 = fmaxf(acc[mt][nt][1] + b1, 0.f);
                    float v2 = fmaxf(acc[mt][nt][2] + b0, 0.f);
                    float v3 = fmaxf(acc[mt][nt][3] + b1, 0.f);
                    uint32_t h, l;
                    split_pack(v0, v1, h, l);
                    Ahi[r * LDA_U + (col >> 1)] = h;
                    Alo[r * LDA_U + (col >> 1)] = l;
                    split_pack(v2, v3, h, l);
                    Ahi[(r + 8) * LDA_U + (col >> 1)] = h;
                    Alo[(r + 8) * LDA_U + (col >> 1)] = l;
                }
            }
            __syncthreads();
        }
    }

    // ---------- score: z2 = relu(acc + bp2); s = z2 . Wp3 ----------
    #pragma unroll
    for (int mt = 0; mt < 2; mt++) {
        float sA = 0.f, sB = 0.f;
        #pragma unroll
        for (int nt = 0; nt < 8; nt++) {
            int col = wc * 64 + nt * 8 + 2 * (lane & 3);
            float b0 = bsm2[col], b1 = bsm2[col + 1];
            float w0 = w3[col],  w1 = w3[col + 1];
            sA += fmaxf(acc[mt][nt][0] + b0, 0.f) * w0 + fmaxf(acc[mt][nt][1] + b1, 0.f) * w1;
            sB += fmaxf(acc[mt][nt][2] + b0, 0.f) * w0 + fmaxf(acc[mt][nt][3] + b1, 0.f) * w1;
        }
        sA += __shfl_xor_sync(0xffffffffu, sA, 1);
        sA += __shfl_xor_sync(0xffffffffu, sA, 2);
        sB += __shfl_xor_sync(0xffffffffu, sB, 1);
        sB += __shfl_xor_sync(0xffffffffu, sB, 2);
        if ((lane & 3) == 0) {
            int r = wr * 32 + (lane >> 2) + mt * 16;
            atomicAdd(&sred[r], sA);
            atomicAdd(&sred[r + 8], sB);
        }
    }
    __syncthreads();
    if (tid < 64) out[blockIdx.x * 64 + tid] = sred[tid];
}

// ---------------- launch ----------------
extern "C" void kernel_launch(void* const* d_in, const int* in_sizes, int n_in,
                              void* d_out, int out_size) {
    const float* node_feat = (const float*)d_in[0];
    const int*   gids0     = (const int*)d_in[1];
    const int*   neigh0    = (const int*)d_in[2];
    const int*   neigh1    = (const int*)d_in[3];
    const float* Ws0       = (const float*)d_in[4];
    const float* Wn0       = (const float*)d_in[5];
    const float* b0        = (const float*)d_in[6];
    const float* Ws1       = (const float*)d_in[7];
    const float* Wn1       = (const float*)d_in[8];
    const float* b1        = (const float*)d_in[9];
    const float* Wp1       = (const float*)d_in[10];
    const float* bp1       = (const float*)d_in[11];
    const float* Wp2       = (const float*)d_in[12];
    const float* bp2       = (const float*)d_in[13];
    const float* Wp3       = (const float*)d_in[14];
    const float* bp3       = (const float*)d_in[15];
    float* out = (float*)d_out;

    float *h0, *h2;
    cudaGetSymbolAddress((void**)&h0, g_h0);
    cudaGetSymbolAddress((void**)&h2, g_h2);

    // smem bytes: 2*A + 2*B + bias + idx
    const int SM128 = (2 * 128 * (128 / 2 + 4) + 2 * 16 * 264 + 256 + 128 * FANC) * 4;  // 109,568
    const int SM256 = (2 * 128 * (256 / 2 + 4) + 2 * 16 * 264 + 256 + 128 * FANC) * 4;  // 175,104
    const int SMMLP = (2 * 64 * 132 + 2 * 16 * 264 + 3 * 256 + 64) * 4;                  // 104,704

    cudaFuncSetAttribute(mma_gemm<0, 128, true >, cudaFuncAttributeMaxDynamicSharedMemorySize, SM128);
    cudaFuncSetAttribute(mma_gemm<1, 256, false>, cudaFuncAttributeMaxDynamicSharedMemorySize, SM256);
    cudaFuncSetAttribute(mlp_fused, cudaFuncAttributeMaxDynamicSharedMemorySize, SMMLP);

    // layer 0: h0 = relu(self@Ws0 + mean@Wn0 + b0)
    mma_gemm<0, 128, true ><<<N1C / 128, 512, SM128>>>(node_feat, gids0, neigh0, Ws0, Wn0, b0, h0);
    // layer 1: h2 = self@Ws1 + mean@Wn1 + b1
    mma_gemm<1, 256, false><<<N2C / 128, 512, SM256>>>(h0, nullptr, neigh1, Ws1, Wn1, b1, h2);
    // fused MLP1+MLP2+score
    mlp_fused<<<(2 * NBAT) / 64, 256, SMMLP>>>(h2, Wp1, bp1, Wp2, bp2, Wp3, bp3, out);
}